// round 7
// baseline (speedup 1.0000x reference)
#include <cuda_runtime.h>
#include <cuda_fp16.h>
#include <mma.h>
#include <math.h>

using namespace nvcuda;

#define B_     16
#define T_     256
#define MEL_   1024
#define D_     512
#define H_     8
#define DH_    64
#define L_     4
#define INTER_ 2048
#define OUT_   80
#define MMAX   (B_*MEL_)

// ---------------- weight fp16 arena offsets ----------------
#define SZ_WQKV (L_*D_*3*D_)
#define SZ_WO   (L_*D_*D_)
#define SZ_C1W  (L_*3*D_*INTER_)
#define SZ_C2W  (L_*3*INTER_*D_)
#define STK     (SZ_WQKV + SZ_WO + SZ_C1W + SZ_C2W)
#define OFF_WO_REL   (SZ_WQKV)
#define OFF_C1_REL   (SZ_WQKV + SZ_WO)
#define OFF_C2_REL   (SZ_WQKV + SZ_WO + SZ_C1W)

// ---------------- device scratch (static: no allocs allowed) ----------------
__device__ half  g_w16[2*STK];
__device__ float g_xf[MMAX*D_];
__device__ half  g_x16[MMAX*D_];
__device__ float g_yf[MMAX*D_];
__device__ half  g_y16[MMAX*D_];
__device__ float g_tmpf[MMAX*D_];
__device__ half  g_qkv16[MMAX*3*D_];
__device__ half  g_ctx16[MMAX*D_];
__device__ half  g_h16[MMAX*INTER_];
__device__ float g_encf[B_*T_*D_];
__device__ int   g_cums[B_*T_];

// ---------------- GEMM parameter block (batch-1, row-major B only) ----------------
struct GP {
    const half* A;  const half* Bm;  float* C;  half* C16;
    const float* bias;  const float* R;
    int M, N, K;
    int lda, ldb, ldc;
    int S;            // sequence length (row block for conv shifting)
    int convK;        // 0 = plain GEMM; else per-slice K (fused 3-tap conv over K)
    int flags;        // 1=beta, 2=write C fp32, 4=relu before C16 write
};

// ---------------- wmma GEMM: double-buffered, fused-conv-K ----------------
// 256 threads, warp grid 4 (rows) x 2 (cols). 128x128x32 tiles.
template<int BMt, int BNt, int BKt>
__global__ __launch_bounds__(256, 2) void gemm_kernel(GP p) {
    constexpr int WM = BMt / 4;            // 32
    constexpr int WN = BNt / 2;            // 64
    constexpr int MI = WM / 16;            // 2
    constexpr int NJ = WN / 16;            // 4
    constexpr int AL = BMt * BKt / 2048;   // uint4 A loads / thread
    constexpr int BL = BKt * BNt / 2048;   // uint4 B loads / thread
    constexpr int NPASS = BNt / 64;
    constexpr int BROW = BNt / 8;

    struct SmemLd { half A[2][BMt][BKt + 8]; half B[2][BKt][BNt + 16]; };
    __shared__ union USm {
        SmemLd ld;
        float Cs[BMt][68];
    } sm;

    const int m0 = blockIdx.y * BMt, n0 = blockIdx.x * BNt;
    const int tid = threadIdx.x, wid = tid >> 5;
    const int wm = (wid & 3) * WM, wn = (wid >> 2) * WN;

    wmma::fragment<wmma::accumulator, 16, 16, 16, float> cf[MI][NJ];
    #pragma unroll
    for (int i = 0; i < MI; i++)
        #pragma unroll
        for (int j = 0; j < NJ; j++) wmma::fill_fragment(cf[i][j], 0.0f);

    // A map: u = tid + i*256; row = u/4; col8 = (u%4)*8
    const half* Aptr[AL];  int arr[AL], ac8[AL], tmod[AL];
    #pragma unroll
    for (int i = 0; i < AL; i++) {
        int u = tid + i * 256;
        arr[i] = u >> 2;  ac8[i] = (u & 3) << 3;
        int grow = m0 + arr[i];
        tmod[i] = grow % p.S;
        Aptr[i] = p.A + (long long)grow * p.lda + ac8[i];
    }
    // B map (row-major): row = u/BROW; col8 = (u%BROW)*8
    int brr[BL], bc8[BL];
    #pragma unroll
    for (int i = 0; i < BL; i++) {
        int u = tid + i * 256;
        brr[i] = u / BROW;  bc8[i] = (u % BROW) << 3;
    }

    const int nIter = p.K / BKt;

    // ---- preload stage 0 ----
    {
        const int rsh = p.convK ? -1 : 0;
        #pragma unroll
        for (int i = 0; i < AL; i++) {
            uint4 av = make_uint4(0u, 0u, 0u, 0u);
            bool ok = !p.convK || ((unsigned)(tmod[i] + rsh) < (unsigned)p.S);
            if (ok) av = *(const uint4*)(Aptr[i] + (long long)rsh * p.lda);
            *(uint4*)(&sm.ld.A[0][arr[i]][ac8[i]]) = av;
        }
        #pragma unroll
        for (int i = 0; i < BL; i++)
            *(uint4*)(&sm.ld.B[0][brr[i]][bc8[i]]) =
                *(const uint4*)(p.Bm + (long long)brr[i] * p.ldb + n0 + bc8[i]);
    }
    __syncthreads();

    for (int it = 0; it < nIter; it++) {
        const int buf = it & 1;
        const bool more = (it + 1 < nIter);
        uint4 avn[AL], bvn[BL];
        if (more) {
            const int k0 = (it + 1) * BKt;
            int sl = 0, colk = k0, rsh = 0;
            if (p.convK) {
                sl = k0 / p.convK;
                colk = k0 - sl * p.convK;
                rsh = sl - 1;
            }
            #pragma unroll
            for (int i = 0; i < AL; i++) {
                avn[i] = make_uint4(0u, 0u, 0u, 0u);
                bool ok = !p.convK || ((unsigned)(tmod[i] + rsh) < (unsigned)p.S);
                if (ok) avn[i] = *(const uint4*)(Aptr[i] + (long long)rsh * p.lda + colk);
            }
            #pragma unroll
            for (int i = 0; i < BL; i++)
                bvn[i] = *(const uint4*)(p.Bm + (long long)(k0 + brr[i]) * p.ldb + n0 + bc8[i]);
        }

        #pragma unroll
        for (int sub = 0; sub < BKt / 16; sub++) {
            wmma::fragment<wmma::matrix_a, 16, 16, 16, half, wmma::row_major> af[MI];
            wmma::fragment<wmma::matrix_b, 16, 16, 16, half, wmma::row_major> bf[NJ];
            #pragma unroll
            for (int i = 0; i < MI; i++)
                wmma::load_matrix_sync(af[i], &sm.ld.A[buf][wm + i * 16][sub * 16], BKt + 8);
            #pragma unroll
            for (int j = 0; j < NJ; j++)
                wmma::load_matrix_sync(bf[j], &sm.ld.B[buf][sub * 16][wn + j * 16], BNt + 16);
            #pragma unroll
            for (int i = 0; i < MI; i++)
                #pragma unroll
                for (int j = 0; j < NJ; j++) wmma::mma_sync(cf[i][j], af[i], bf[j], cf[i][j]);
        }

        if (more) {
            const int nb = buf ^ 1;
            #pragma unroll
            for (int i = 0; i < AL; i++) *(uint4*)(&sm.ld.A[nb][arr[i]][ac8[i]]) = avn[i];
            #pragma unroll
            for (int i = 0; i < BL; i++) *(uint4*)(&sm.ld.B[nb][brr[i]][bc8[i]]) = bvn[i];
        }
        __syncthreads();
    }

    // ---- epilogue: 64-column passes through aliased Cs ----
    #pragma unroll
    for (int pass = 0; pass < NPASS; pass++) {
        const int lcol = wn - pass * 64;
        if (lcol >= 0 && lcol + WN <= 64) {
            #pragma unroll
            for (int i = 0; i < MI; i++)
                #pragma unroll
                for (int j = 0; j < NJ; j++)
                    wmma::store_matrix_sync(&sm.Cs[wm + i * 16][lcol + j * 16], cf[i][j], 68,
                                            wmma::mem_row_major);
        }
        __syncthreads();

        const int cc = (tid & 15) * 4;
        const int gc = n0 + pass * 64 + cc;
        #pragma unroll
        for (int step = 0; step < BMt / 16; step++) {
            const int row = step * 16 + (tid >> 4);
            const int gr = m0 + row;
            float4 v = *(const float4*)(&sm.Cs[row][cc]);
            if (p.bias) {
                float4 bb = *(const float4*)(p.bias + gc);
                v.x += bb.x; v.y += bb.y; v.z += bb.z; v.w += bb.w;
            }
            const long long ci = (long long)gr * p.ldc + gc;
            if (p.flags & 1) {
                float4 c0 = *(const float4*)(p.C + ci);
                v.x += c0.x; v.y += c0.y; v.z += c0.z; v.w += c0.w;
            }
            if (p.R) {
                float4 r0 = *(const float4*)(p.R + ci);
                v.x += r0.x; v.y += r0.y; v.z += r0.z; v.w += r0.w;
            }
            if (p.flags & 2) *(float4*)(p.C + ci) = v;
            if (p.C16) {
                float4 w = v;
                if (p.flags & 4) {
                    w.x = fmaxf(w.x, 0.0f); w.y = fmaxf(w.y, 0.0f);
                    w.z = fmaxf(w.z, 0.0f); w.w = fmaxf(w.w, 0.0f);
                }
                half2 h0 = __floats2half2_rn(w.x, w.y);
                half2 h1 = __floats2half2_rn(w.z, w.w);
                uint2 pk = make_uint2(*(unsigned*)&h0, *(unsigned*)&h1);
                *(uint2*)(p.C16 + ci) = pk;
            }
        }
        if (pass + 1 < NPASS) __syncthreads();
    }
}

// ---------------- fused two-pass flash attention ----------------
// grid: (S/64, H, B), 128 threads (4 warps). Warp w owns q-rows [w*16, w*16+16).
// Fully-masked K tiles (kt*64 > len) are skipped: they contribute nothing.
__global__ __launch_bounds__(128) void flash_kernel(
    const half* __restrict__ qkv, half* __restrict__ ctx,
    const int* __restrict__ lens, int S)
{
    __shared__ half  Qsm[64][72];
    __shared__ half  Ksm[64][72];   // doubles as P tile in pass 2
    __shared__ half  Vsm[64][72];
    __shared__ float Ssm[64][68];

    const int qt = blockIdx.x, h = blockIdx.y, b = blockIdx.z;
    const int q0 = qt * 64;
    const int len = lens[b];
    const int tid = threadIdx.x;
    const int wid = tid >> 5;
    const int r  = tid >> 1;        // 0..63
    const int c0 = (tid & 1) * 32;

    const int rowstride = 3 * D_;
    const half* base = qkv + (long long)(b * S) * rowstride + h * DH_;

    // load Q tile once
    {
        const half* src = base + (long long)(q0 + r) * rowstride + c0;
        #pragma unroll
        for (int i = 0; i < 4; i++)
            *(uint4*)(&Qsm[r][c0 + 8 * i]) = *(const uint4*)(src + 8 * i);
    }
    __syncthreads();

    const float scale = 0.125f;
    const int nkt = S / 64;
    // number of live K tiles: indices 0..len valid -> ceil((len+1)/64)
    const int nlive = (len + 64) >> 6;
    const int nk = nlive < nkt ? nlive : nkt;
    float m = -1e30f, l = 0.0f;

    // ---------- pass 1: softmax stats ----------
    for (int kt = 0; kt < nk; kt++) {
        {
            const half* src = base + D_ + (long long)(kt * 64 + r) * rowstride + c0;
            #pragma unroll
            for (int i = 0; i < 4; i++)
                *(uint4*)(&Ksm[r][c0 + 8 * i]) = *(const uint4*)(src + 8 * i);
        }
        __syncthreads();

        {   // S strip = Q(16xDH) @ K^T
            wmma::fragment<wmma::accumulator, 16, 16, 16, float> sf[4];
            #pragma unroll
            for (int j = 0; j < 4; j++) wmma::fill_fragment(sf[j], 0.0f);
            #pragma unroll
            for (int d = 0; d < 4; d++) {
                wmma::fragment<wmma::matrix_a, 16, 16, 16, half, wmma::row_major> qa;
                wmma::load_matrix_sync(qa, &Qsm[wid * 16][d * 16], 72);
                #pragma unroll
                for (int j = 0; j < 4; j++) {
                    wmma::fragment<wmma::matrix_b, 16, 16, 16, half, wmma::col_major> kb;
                    wmma::load_matrix_sync(kb, &Ksm[j * 16][d * 16], 72);
                    wmma::mma_sync(sf[j], qa, kb, sf[j]);
                }
            }
            #pragma unroll
            for (int j = 0; j < 4; j++)
                wmma::store_matrix_sync(&Ssm[wid * 16][j * 16], sf[j], 68, wmma::mem_row_major);
        }
        __syncthreads();

        {   // per-row online stats (2 threads per row, partner = lane^1)
            const int kb0 = kt * 64 + c0;
            float lm = -1e30f;
            #pragma unroll 8
            for (int c = 0; c < 32; c++)
                if (kb0 + c <= len) lm = fmaxf(lm, Ssm[r][c0 + c] * scale);
            lm = fmaxf(lm, __shfl_xor_sync(~0u, lm, 1));
            float mnew = fmaxf(m, lm);
            float sum = 0.0f;
            if (mnew > -1e29f) {
                #pragma unroll 8
                for (int c = 0; c < 32; c++)
                    if (kb0 + c <= len) sum += __expf(Ssm[r][c0 + c] * scale - mnew);
            }
            sum += __shfl_xor_sync(~0u, sum, 1);
            l = l * __expf(m - mnew) + sum;
            m = mnew;
        }
        __syncthreads();
    }
    const float linv = 1.0f / l;

    // ---------- pass 2: O accumulation ----------
    wmma::fragment<wmma::accumulator, 16, 16, 16, float> of[4];
    #pragma unroll
    for (int j = 0; j < 4; j++) wmma::fill_fragment(of[j], 0.0f);

    for (int kt = 0; kt < nk; kt++) {
        {
            const half* srck = base + D_     + (long long)(kt * 64 + r) * rowstride + c0;
            const half* srcv = base + 2 * D_ + (long long)(kt * 64 + r) * rowstride + c0;
            #pragma unroll
            for (int i = 0; i < 4; i++) {
                *(uint4*)(&Ksm[r][c0 + 8 * i]) = *(const uint4*)(srck + 8 * i);
                *(uint4*)(&Vsm[r][c0 + 8 * i]) = *(const uint4*)(srcv + 8 * i);
            }
        }
        __syncthreads();

        {   // recompute S
            wmma::fragment<wmma::accumulator, 16, 16, 16, float> sf[4];
            #pragma unroll
            for (int j = 0; j < 4; j++) wmma::fill_fragment(sf[j], 0.0f);
            #pragma unroll
            for (int d = 0; d < 4; d++) {
                wmma::fragment<wmma::matrix_a, 16, 16, 16, half, wmma::row_major> qa;
                wmma::load_matrix_sync(qa, &Qsm[wid * 16][d * 16], 72);
                #pragma unroll
                for (int j = 0; j < 4; j++) {
                    wmma::fragment<wmma::matrix_b, 16, 16, 16, half, wmma::col_major> kb;
                    wmma::load_matrix_sync(kb, &Ksm[j * 16][d * 16], 72);
                    wmma::mma_sync(sf[j], qa, kb, sf[j]);
                }
            }
            #pragma unroll
            for (int j = 0; j < 4; j++)
                wmma::store_matrix_sync(&Ssm[wid * 16][j * 16], sf[j], 68, wmma::mem_row_major);
        }
        __syncthreads();

        {   // P tile (fp16) overlays K tile (done with K this iter)
            const int kb0 = kt * 64 + c0;
            #pragma unroll 8
            for (int c = 0; c < 32; c++) {
                float pv = 0.0f;
                if (kb0 + c <= len) pv = __expf(Ssm[r][c0 + c] * scale - m) * linv;
                Ksm[r][c0 + c] = __float2half(pv);
            }
        }
        __syncthreads();

        {   // O += P @ V
            #pragma unroll
            for (int kk = 0; kk < 4; kk++) {
                wmma::fragment<wmma::matrix_a, 16, 16, 16, half, wmma::row_major> pa;
                wmma::load_matrix_sync(pa, &Ksm[wid * 16][kk * 16], 72);
                #pragma unroll
                for (int j = 0; j < 4; j++) {
                    wmma::fragment<wmma::matrix_b, 16, 16, 16, half, wmma::row_major> vb;
                    wmma::load_matrix_sync(vb, &Vsm[kk * 16][j * 16], 72);
                    wmma::mma_sync(of[j], pa, vb, of[j]);
                }
            }
        }
        __syncthreads();
    }

    // write ctx
    #pragma unroll
    for (int j = 0; j < 4; j++)
        wmma::store_matrix_sync(&Ssm[wid * 16][j * 16], of[j], 68, wmma::mem_row_major);
    __syncthreads();
    {
        half* dst = ctx + (long long)(b * S + q0 + r) * D_ + h * DH_ + c0;
        #pragma unroll
        for (int c = 0; c < 32; c += 2) {
            half2 hp = __floats2half2_rn(Ssm[r][c0 + c], Ssm[r][c0 + c + 1]);
            *(half2*)(dst + c) = hp;
        }
    }
}

// ---------------- LayerNorm (D=512, 128 threads, writes fp32 + fp16) ----------------
__global__ void ln_kernel(const float* __restrict__ in, const float* __restrict__ g,
                          const float* __restrict__ bt, float* outf, half* o16) {
    __shared__ float rs_[4], rq_[4];
    int row = blockIdx.x, tid = threadIdx.x;
    const float* x = in + (long long)row * D_;
    float4 xv = *(const float4*)(x + tid * 4);
    float s = xv.x + xv.y + xv.z + xv.w;
    float q = xv.x * xv.x + xv.y * xv.y + xv.z * xv.z + xv.w * xv.w;
    #pragma unroll
    for (int o = 16; o; o >>= 1) {
        s += __shfl_xor_sync(~0u, s, o);
        q += __shfl_xor_sync(~0u, q, o);
    }
    if ((tid & 31) == 0) { rs_[tid >> 5] = s; rq_[tid >> 5] = q; }
    __syncthreads();
    s = rs_[0] + rs_[1] + rs_[2] + rs_[3];
    q = rq_[0] + rq_[1] + rq_[2] + rq_[3];
    float mean = s * (1.0f / D_);
    float var = q * (1.0f / D_) - mean * mean;
    float rstd = rsqrtf(var + 1e-5f);

    int d = tid * 4;
    float4 gv = *(const float4*)(g + d);
    float4 bv = *(const float4*)(bt + d);
    float4 o;
    o.x = (xv.x - mean) * rstd * gv.x + bv.x;
    o.y = (xv.y - mean) * rstd * gv.y + bv.y;
    o.z = (xv.z - mean) * rstd * gv.z + bv.z;
    o.w = (xv.w - mean) * rstd * gv.w + bv.w;
    if (outf) *(float4*)(outf + (long long)row * D_ + d) = o;
    if (o16) {
        half2 a = __floats2half2_rn(o.x, o.y);
        half2 b = __floats2half2_rn(o.z, o.w);
        uint2 pk = make_uint2(*(unsigned*)&a, *(unsigned*)&b);
        *(uint2*)(o16 + (long long)row * D_ + d) = pk;
    }
}

// ---------------- embedding + positional add (pos indexed by BATCH per ref) ----------------
__global__ void embed_kernel(const int* __restrict__ tokens, const float* __restrict__ emb,
                             float* xf, half* x16) {
    int row = blockIdx.x;      // B_*T_
    int b = row / T_;
    int tok = tokens[row];
    int d = threadIdx.x * 4;
    float4 ev = *(const float4*)(emb + (long long)tok * D_ + d);
    float o[4];
    const float LOGC = 0.017988946039015984f;  // ln(10000)/512
    #pragma unroll
    for (int j = 0; j < 4; j++) {
        int dd = d + j;
        float k2 = (float)(dd & ~1);
        float den = __expf(-k2 * LOGC);
        float ang = (float)b * den;
        float pv = (dd & 1) ? cosf(ang) : sinf(ang);
        o[j] = 2.0f * ((const float*)&ev)[j] + pv;
    }
    float4 ov = make_float4(o[0], o[1], o[2], o[3]);
    *(float4*)(xf + (long long)row * D_ + d) = ov;
    half2 a = __floats2half2_rn(o[0], o[1]);
    half2 b2 = __floats2half2_rn(o[2], o[3]);
    uint2 pk = make_uint2(*(unsigned*)&a, *(unsigned*)&b2);
    *(uint2*)(x16 + (long long)row * D_ + d) = pk;
}

// ---------------- duration cumsum + gather (length regulator) ----------------
__global__ void cumsum_kernel(const int* __restrict__ dur, int* cums) {
    int b = threadIdx.x;
    if (b < B_) {
        int s = 0;
        for (int t = 0; t < T_; t++) { s += dur[b * T_ + t]; cums[b * T_ + t] = s; }
    }
}

__global__ void gather_kernel(const int* __restrict__ cums, const int* __restrict__ mlen,
                              const float* __restrict__ enc, float* xf, half* x16) {
    int row = blockIdx.x;    // B_*MEL_
    int b = row / MEL_;
    int f = row % MEL_;
    const int* c = cums + b * T_;
    int lo = 0, hi = T_;
    while (lo < hi) { int mid = (lo + hi) >> 1; if (c[mid] <= f) lo = mid + 1; else hi = mid; }
    int idx = lo < T_ ? lo : (T_ - 1);
    float keep = (f <= mlen[b]) ? 1.0f : 0.0f;
    const float* src = enc + ((long long)(b * T_ + idx)) * D_;
    int d = threadIdx.x * 4;
    float4 v = *(const float4*)(src + d);
    v.x *= keep; v.y *= keep; v.z *= keep; v.w *= keep;
    *(float4*)(xf + (long long)row * D_ + d) = v;
    half2 a = __floats2half2_rn(v.x, v.y);
    half2 b2 = __floats2half2_rn(v.z, v.w);
    uint2 pk = make_uint2(*(unsigned*)&a, *(unsigned*)&b2);
    *(uint2*)(x16 + (long long)row * D_ + d) = pk;
}

// ---------------- fused fp32 output projection + transpose ----------------
__global__ void outproj_kernel(const float* __restrict__ x, const float* __restrict__ w,
                               const float* __restrict__ bias, float* __restrict__ out) {
    __shared__ float xs[D_];
    int row = blockIdx.x;              // b*MEL + t
    int b = row / MEL_, t = row % MEL_;
    for (int i = threadIdx.x; i < D_; i += 128)
        xs[i] = x[(long long)row * D_ + i];
    __syncthreads();
    int n = threadIdx.x;
    if (n < OUT_) {
        float acc = bias[n];
        #pragma unroll 8
        for (int k = 0; k < D_; k++) acc = fmaf(xs[k], w[k * OUT_ + n], acc);
        out[((long long)b * OUT_ + n) * MEL_ + t] = acc;
    }
}

// ---------------- fp32 -> fp16 weight convert ----------------
__global__ void cvt_kernel(const float* __restrict__ s, half* __restrict__ d, int n4) {
    int i = blockIdx.x * 256 + threadIdx.x;
    if (i < n4) {
        float4 v = ((const float4*)s)[i];
        half2 a = __floats2half2_rn(v.x, v.y);
        half2 b = __floats2half2_rn(v.z, v.w);
        uint2 pk = make_uint2(*(unsigned*)&a, *(unsigned*)&b);
        ((uint2*)d)[i] = pk;
    }
}

// ================= host side =================

struct Bufs {
    half* w16;
    float *xf, *yf, *tmpf, *encf;
    half *x16, *y16, *qkv16, *ctx16, *h16;
    int* cums;
};

static void launch_gemm(const GP& p) {
    dim3 grid(p.N / 128, p.M / 128, 1);
    gemm_kernel<128, 128, 32><<<grid, 256>>>(p);
}

static void run_stack(const float* const* P, const half* wstk, int S, int M,
                      const int* lens, const Bufs& b, float* final_f, half* final_h) {
    for (int l = 0; l < L_; l++) {
        const half* wq = wstk + (size_t)l * D_ * 3 * D_;
        const half* wo = wstk + OFF_WO_REL + (size_t)l * D_ * D_;
        const half* c1 = wstk + OFF_C1_REL + (size_t)l * 3 * D_ * INTER_;
        const half* c2 = wstk + OFF_C2_REL + (size_t)l * 3 * INTER_ * D_;

        // qkv = x @ wqkv + bqkv  (fp16 out only)
        { GP g{}; g.A = b.x16; g.lda = D_; g.Bm = wq; g.ldb = 3 * D_;
          g.C16 = b.qkv16; g.ldc = 3 * D_; g.bias = P[1] + l * 3 * D_;
          g.M = M; g.N = 3 * D_; g.K = D_; g.S = M; launch_gemm(g); }

        // fused flash attention: qkv16 -> ctx16
        flash_kernel<<<dim3(S / 64, H_, B_), 128>>>(b.qkv16, b.ctx16, lens, S);

        // tmp = ctx @ wo + bo + x
        { GP g{}; g.A = b.ctx16; g.lda = D_; g.Bm = wo; g.ldb = D_;
          g.C = b.tmpf; g.ldc = D_; g.bias = P[3] + l * D_; g.R = b.xf;
          g.flags = 2; g.M = M; g.N = D_; g.K = D_; g.S = M; launch_gemm(g); }

        ln_kernel<<<M, 128>>>(b.tmpf, P[4] + l * D_, P[5] + l * D_, b.yf, b.y16);

        // conv1 fused (K=3*D, per-slice row shift): h16 = relu(conv1(y) + c1b)
        { GP g{}; g.A = b.y16; g.lda = D_; g.Bm = c1; g.ldb = INTER_;
          g.C16 = b.h16; g.ldc = INTER_; g.bias = P[7] + l * INTER_;
          g.flags = 4; g.M = M; g.N = INTER_; g.K = 3 * D_; g.convK = D_;
          g.S = S; launch_gemm(g); }

        // conv2 fused: tmp = conv2(h16) + c2b + y
        { GP g{}; g.A = b.h16; g.lda = INTER_; g.Bm = c2; g.ldb = D_;
          g.C = b.tmpf; g.ldc = D_; g.bias = P[9] + l * D_; g.R = b.yf;
          g.flags = 2; g.M = M; g.N = D_; g.K = 3 * INTER_; g.convK = INTER_;
          g.S = S; launch_gemm(g); }

        float* of = (l == L_ - 1) ? final_f : b.xf;
        half*  oh = (l == L_ - 1) ? final_h : b.x16;
        ln_kernel<<<M, 128>>>(b.tmpf, P[10] + l * D_, P[11] + l * D_, of, oh);
    }
}

extern "C" void kernel_launch(void* const* d_in, const int* in_sizes, int n_in,
                              void* d_out, int out_size) {
    const int* tokens = (const int*)d_in[0];
    const int* tlen   = (const int*)d_in[1];
    const int* mlen   = (const int*)d_in[2];
    const int* dur    = (const int*)d_in[3];
    int ei = n_in - 27;                       // emb is 27th from the end
    const float* emb = (const float*)d_in[ei];
    const float* encP[12], *decP[12];
    for (int j = 0; j < 12; j++) encP[j] = (const float*)d_in[ei + 1 + j];
    for (int j = 0; j < 12; j++) decP[j] = (const float*)d_in[ei + 13 + j];
    const float* outw = (const float*)d_in[ei + 25];
    const float* outb = (const float*)d_in[ei + 26];

    Bufs b;
    cudaGetSymbolAddress((void**)&b.w16,   g_w16);
    cudaGetSymbolAddress((void**)&b.xf,    g_xf);
    cudaGetSymbolAddress((void**)&b.x16,   g_x16);
    cudaGetSymbolAddress((void**)&b.yf,    g_yf);
    cudaGetSymbolAddress((void**)&b.y16,   g_y16);
    cudaGetSymbolAddress((void**)&b.tmpf,  g_tmpf);
    cudaGetSymbolAddress((void**)&b.qkv16, g_qkv16);
    cudaGetSymbolAddress((void**)&b.ctx16, g_ctx16);
    cudaGetSymbolAddress((void**)&b.h16,   g_h16);
    cudaGetSymbolAddress((void**)&b.encf,  g_encf);
    cudaGetSymbolAddress((void**)&b.cums,  g_cums);

    // fp16 weight conversion (per-launch; deterministic)
    auto cvt = [](const float* s, half* d, size_t n) {
        int n4 = (int)(n / 4);
        cvt_kernel<<<(n4 + 255) / 256, 256>>>(s, d, n4);
    };
    cvt(encP[0], b.w16,                (size_t)SZ_WQKV);
    cvt(encP[2], b.w16 + OFF_WO_REL,   (size_t)SZ_WO);
    cvt(encP[6], b.w16 + OFF_C1_REL,   (size_t)SZ_C1W);
    cvt(encP[8], b.w16 + OFF_C2_REL,   (size_t)SZ_C2W);
    cvt(decP[0], b.w16 + STK,              (size_t)SZ_WQKV);
    cvt(decP[2], b.w16 + STK + OFF_WO_REL, (size_t)SZ_WO);
    cvt(decP[6], b.w16 + STK + OFF_C1_REL, (size_t)SZ_C1W);
    cvt(decP[8], b.w16 + STK + OFF_C2_REL, (size_t)SZ_C2W);

    // embedding + pos
    embed_kernel<<<B_ * T_, 128>>>(tokens, emb, b.xf, b.x16);

    // encoder (S=256): final LN writes g_encf (fp32 only)
    run_stack(encP, b.w16, T_, B_ * T_, tlen, b, b.encf, nullptr);

    // length regulator
    cumsum_kernel<<<1, B_>>>(dur, b.cums);
    gather_kernel<<<B_ * MEL_, 128>>>(b.cums, mlen, b.encf, b.xf, b.x16);

    // decoder (S=1024): final LN writes xf only (fp32 feeds out-proj)
    run_stack(decP, b.w16 + STK, MEL_, B_ * MEL_, mlen, b, b.xf, nullptr);

    // fused fp32 projection + transpose: out[b,n,t]
    outproj_kernel<<<B_ * MEL_, 128>>>(b.xf, outw, outb, (float*)d_out);
}